// round 11
// baseline (speedup 1.0000x reference)
#include <cuda_runtime.h>
#include <math.h>
#include <stdint.h>

#define BS   8
#define LSEQ 8192
#define D    128
#define H    128
#define NTOK (BS * LSEQ)
#define CL   128
#define NCH  (LSEQ / CL)   // 64

#define STRIDE    132                       // floats per smem A-tile row
#define TILE_B    (128 * STRIDE * 4)        // 67584 bytes
#define OFF_BIAS  0
#define OFF_A     4096
#define OFF_C     (OFF_A + TILE_B)
#define SMEM_FR   (OFF_A + TILE_B)          // 71680: bias + one tile
#define SMEM_MLP  (OFF_C + TILE_B)          // 139264: bias + two tiles

// ---------------- device scratch ----------------
__device__ __align__(16) float g_scal[BS][6];
__device__ __align__(16) float g_loga[H];          // log2(a)
__device__ __align__(16) float g_WT[13][16384];    // fragment-permuted tf32 weights
__device__ __align__(16) float g_at[(size_t)NTOK * H];
__device__ __align__(16) float g_bt[(size_t)NTOK * H];
__device__ __align__(16) float g_x1[(size_t)NTOK * D];
__device__ __align__(16) float g_A [BS * NCH * H];
__device__ __align__(16) float g_Bf[BS * NCH * H];
__device__ __align__(16) float g_Bb[BS * NCH * H];

// ---------------- helpers ----------------
__device__ __forceinline__ float to_tf32(float x) {
    uint32_t u;
    asm("cvt.rna.tf32.f32 %0, %1;" : "=r"(u) : "f"(x));
    return __uint_as_float(u);
}
__device__ __forceinline__ float fast_ex2(float x) { float y; asm("ex2.approx.f32 %0, %1;" : "=f"(y) : "f"(x)); return y; }
__device__ __forceinline__ float fast_rcp(float x) { float y; asm("rcp.approx.f32 %0, %1;" : "=f"(y) : "f"(x)); return y; }
__device__ __forceinline__ float sigf(float v) { return fast_rcp(1.f + fast_ex2(-1.4426950408889634f * v)); }
__device__ __forceinline__ float tanh_(float x) { return 1.f - 2.f * fast_rcp(1.f + fast_ex2(2.8853900817779268f * x)); }
__device__ __forceinline__ float geluf_(float v) {
    float v3 = v * v * v;
    return 0.5f * v * (1.f + tanh_(0.7978845608028654f * (v + 0.044715f * v3)));
}
__device__ __forceinline__ float warp_sum(float v) {
    v += __shfl_xor_sync(0xffffffffu, v, 16);
    v += __shfl_xor_sync(0xffffffffu, v, 8);
    v += __shfl_xor_sync(0xffffffffu, v, 4);
    v += __shfl_xor_sync(0xffffffffu, v, 2);
    v += __shfl_xor_sync(0xffffffffu, v, 1);
    return v;
}

#define MMA168(c, a, b0, b1)                                                        \
    asm volatile("mma.sync.aligned.m16n8k8.row.col.f32.tf32.tf32.f32 "              \
                 "{%0,%1,%2,%3}, {%4,%5,%6,%7}, {%8,%9}, {%0,%1,%2,%3};"            \
                 : "+f"((c)[0]), "+f"((c)[1]), "+f"((c)[2]), "+f"((c)[3])           \
                 : "r"((a)[0]), "r"((a)[1]), "r"((a)[2]), "r"((a)[3]),              \
                   "r"(b0), "r"(b1))

#define ZACC(a) do {                                                                \
    _Pragma("unroll") for (int _m = 0; _m < 2; ++_m)                                \
    _Pragma("unroll") for (int _n = 0; _n < 4; ++_n)                                \
    _Pragma("unroll") for (int _q = 0; _q < 4; ++_q) (a)[_m][_n][_q] = 0.f;         \
} while (0)

// warp GEMM: 32x32 patch of C(128x128) += A(smem) * B(global, fragment-permuted)
__device__ __forceinline__ void wgemm_g(const float* __restrict__ sA,
                                        const float* __restrict__ gB,
                                        float (&acc)[2][4][4],
                                        int wm, int wn, int lane) {
    int tr = lane >> 2, tc = lane & 3;
#pragma unroll 4
    for (int ks = 0; ks < 16; ++ks) {
        int k0 = ks * 8;
        uint32_t a[2][4];
#pragma unroll
        for (int mt = 0; mt < 2; ++mt) {
            const float* ap = sA + (wm * 32 + mt * 16 + tr) * STRIDE + k0 + tc;
            a[mt][0] = __float_as_uint(ap[0]);
            a[mt][1] = __float_as_uint(ap[8 * STRIDE]);
            a[mt][2] = __float_as_uint(ap[4]);
            a[mt][3] = __float_as_uint(ap[8 * STRIDE + 4]);
        }
#pragma unroll
        for (int nt = 0; nt < 4; ++nt) {
            float2 bv = __ldg((const float2*)(gB + ((((wn * 4 + nt) * 16 + ks) << 6) + lane * 2)));
            uint32_t b0 = __float_as_uint(bv.x), b1 = __float_as_uint(bv.y);
#pragma unroll
            for (int mt = 0; mt < 2; ++mt) MMA168(acc[mt][nt], a[mt], b0, b1);
        }
    }
}

// ---------------- K0: conditioning scalars + log2(a) ----------------
__global__ void k_scal(const float* __restrict__ c,
                       const float* sw1, const float* sb1, const float* bw1, const float* bb1,
                       const float* gw1, const float* gb1, const float* sw2, const float* sb2,
                       const float* bw2, const float* bb2, const float* gw2, const float* gb2,
                       const float* __restrict__ a) {
    int tid = threadIdx.x;
    if (tid < 48) {
        const float* ws[6] = {sw1, bw1, gw1, sw2, bw2, gw2};
        const float* bs[6] = {sb1, bb1, gb1, sb2, bb2, gb2};
        int b = tid / 6, j = tid % 6;
        float s = bs[j][0];
        const float* cp = c + b * 128;
        for (int k = 0; k < 128; ++k) s = fmaf(cp[k], ws[j][k], s);
        g_scal[b][j] = s;
    }
    int i = tid - 64;
    if (i >= 0 && i < H) g_loga[i] = log2f(a[i]);
}

// ---------------- K-prep: fragment-permuted tf32 weight tiles ----------------
// value (n, k) of tile t -> offset ((n>>3)*16 + (k>>3))*64 + ((n&7)*4 + (k&3))*2 + ((k>>2)&1)
__global__ void k_prep(const float* __restrict__ Win, const float* __restrict__ Wi,
                       const float* __restrict__ Wr, const float* __restrict__ Wout,
                       const float* __restrict__ W1, const float* __restrict__ W2) {
    int t = blockIdx.x >> 2, quarter = blockIdx.x & 3, tid = threadIdx.x;
    for (int i = quarter * 16; i < quarter * 16 + 16; ++i) {
        int e = i * 256 + tid;
        int n = e >> 7, k = e & 127;
        float v;
        if (t == 0)      v = Win[k * 128 + n];
        else if (t == 1) v = Wi[k * 128 + n];
        else if (t == 2) v = Wr[k * 128 + n];
        else if (t == 3) v = Wout[k * 128 + n];
        else if (t == 4) v = Wout[(128 + k) * 128 + n];
        else if (t < 9)  v = W1[k * 512 + (t - 5) * 128 + n];
        else             v = W2[((t - 9) * 128 + k) * 128 + n];
        int off = (((n >> 3) * 16 + (k >> 3)) << 6) + (((n & 7) << 2) + (k & 3)) * 2 + ((k >> 2) & 1);
        g_WT[t][off] = to_tf32(v);
    }
}

// ---------------- K1: x -> (at, bt) + chunk scan aggregates ----------------
__global__ __launch_bounds__(512) void k_front(
    const float* __restrict__ x, const float* __restrict__ pos,
    const float* __restrict__ inb, const float* __restrict__ bi,
    const float* __restrict__ br) {
    extern __shared__ char sm[];
    float* sBias = (float*)(sm + OFF_BIAS);
    float* sA = (float*)(sm + OFF_A);
    int tid = threadIdx.x, wid = tid >> 5, lane = tid & 31;
    int wm = wid & 3, wn = wid >> 2, tr = lane >> 2, tc = lane & 3;
    int n0 = blockIdx.x * 128;
    int b = n0 >> 13, l0 = n0 & (LSEQ - 1);
    if (tid < 128) {
        sBias[tid] = inb[tid]; sBias[128 + tid] = bi[tid];
        sBias[256 + tid] = br[tid]; sBias[384 + tid] = g_loga[tid];
    }
    float s1p = 1.f + g_scal[b][0], b1s = g_scal[b][1];

    // conditioned double-LN -> tf32 A tile
#pragma unroll
    for (int it = 0; it < 8; ++it) {
        int row = wid * 8 + it;
        const float* xp = x + (size_t)(n0 + row) * D;
        float v0 = xp[lane], v1 = xp[lane + 32], v2 = xp[lane + 64], v3 = xp[lane + 96];
        float m = warp_sum(v0 + v1 + v2 + v3) * (1.f / 128.f);
        float d0 = v0 - m, d1 = v1 - m, d2 = v2 - m, d3 = v3 - m;
        float rs = rsqrtf(warp_sum(d0*d0 + d1*d1 + d2*d2 + d3*d3) * (1.f / 128.f) + 1e-6f);
        float h0 = fmaf(s1p, d0 * rs, b1s), h1 = fmaf(s1p, d1 * rs, b1s);
        float h2 = fmaf(s1p, d2 * rs, b1s), h3 = fmaf(s1p, d3 * rs, b1s);
        float m2 = warp_sum(h0 + h1 + h2 + h3) * (1.f / 128.f);
        float e0 = h0 - m2, e1 = h1 - m2, e2 = h2 - m2, e3 = h3 - m2;
        float rs2 = rsqrtf(warp_sum(e0*e0 + e1*e1 + e2*e2 + e3*e3) * (1.f / 128.f) + 1e-6f);
        float* ap = sA + row * STRIDE;
        ap[lane]      = to_tf32(e0 * rs2);
        ap[lane + 32] = to_tf32(e1 * rs2);
        ap[lane + 64] = to_tf32(e2 * rs2);
        ap[lane + 96] = to_tf32(e3 * rs2);
    }
    __syncthreads();

    float uacc[2][4][4];
    ZACC(uacc);
    wgemm_g(sA, g_WT[0], uacc, wm, wn, lane);
    __syncthreads();                       // all warps done reading sA (ln2)

    // u = gemm + bias + pos -> tf32 back into sA
#pragma unroll
    for (int mt = 0; mt < 2; ++mt)
#pragma unroll
        for (int nt = 0; nt < 4; ++nt) {
            int r = wm * 32 + mt * 16 + tr, c = wn * 32 + nt * 8 + tc * 2;
            float2 p0 = *(const float2*)(pos + (size_t)(l0 + r) * H + c);
            float2 p1 = *(const float2*)(pos + (size_t)(l0 + r + 8) * H + c);
            sA[r * STRIDE + c]           = to_tf32(uacc[mt][nt][0] + sBias[c]     + p0.x);
            sA[r * STRIDE + c + 1]       = to_tf32(uacc[mt][nt][1] + sBias[c + 1] + p0.y);
            sA[(r + 8) * STRIDE + c]     = to_tf32(uacc[mt][nt][2] + sBias[c]     + p1.x);
            sA[(r + 8) * STRIDE + c + 1] = to_tf32(uacc[mt][nt][3] + sBias[c + 1] + p1.y);
        }
    __syncthreads();

    float gacc[2][4][4];
    ZACC(gacc);
    wgemm_g(sA, g_WT[1], gacc, wm, wn, lane);   // input gate pre-activation
#pragma unroll
    for (int mt = 0; mt < 2; ++mt)
#pragma unroll
        for (int nt = 0; nt < 4; ++nt) {
            int c = wn * 32 + nt * 8 + tc * 2;
            gacc[mt][nt][0] = sigf(gacc[mt][nt][0] + sBias[128 + c]);
            gacc[mt][nt][1] = sigf(gacc[mt][nt][1] + sBias[128 + c + 1]);
            gacc[mt][nt][2] = sigf(gacc[mt][nt][2] + sBias[128 + c]);
            gacc[mt][nt][3] = sigf(gacc[mt][nt][3] + sBias[128 + c + 1]);
        }
    float racc[2][4][4];
    ZACC(racc);
    wgemm_g(sA, g_WT[2], racc, wm, wn, lane);   // recurrence gate pre-activation

#pragma unroll
    for (int mt = 0; mt < 2; ++mt)
#pragma unroll
        for (int nt = 0; nt < 4; ++nt) {
            int r = wm * 32 + mt * 16 + tr, c = wn * 32 + nt * 8 + tc * 2;
            float2 u0 = *(const float2*)(sA + r * STRIDE + c);
            float2 u1 = *(const float2*)(sA + (r + 8) * STRIDE + c);
            float la0 = sBias[384 + c], la1 = sBias[384 + c + 1];
            float gr0 = sigf(racc[mt][nt][0] + sBias[256 + c]);
            float gr1 = sigf(racc[mt][nt][1] + sBias[256 + c + 1]);
            float gr2 = sigf(racc[mt][nt][2] + sBias[256 + c]);
            float gr3 = sigf(racc[mt][nt][3] + sBias[256 + c + 1]);
            float a0 = fast_ex2(8.f * gr0 * la0);
            float a1 = fast_ex2(8.f * gr1 * la1);
            float a2 = fast_ex2(8.f * gr2 * la0);
            float a3 = fast_ex2(8.f * gr3 * la1);
            float b0v = sqrtf(fmaxf(0.f, 1.f - a0 * a0)) * gacc[mt][nt][0] * u0.x;
            float b1v = sqrtf(fmaxf(0.f, 1.f - a1 * a1)) * gacc[mt][nt][1] * u0.y;
            float b2v = sqrtf(fmaxf(0.f, 1.f - a2 * a2)) * gacc[mt][nt][2] * u1.x;
            float b3v = sqrtf(fmaxf(0.f, 1.f - a3 * a3)) * gacc[mt][nt][3] * u1.y;
            size_t o0 = (size_t)(n0 + r) * H + c, o1 = (size_t)(n0 + r + 8) * H + c;
            *(float2*)(g_at + o0) = make_float2(a0, a1);
            *(float2*)(g_at + o1) = make_float2(a2, a3);
            *(float2*)(g_bt + o0) = make_float2(b0v, b1v);
            *(float2*)(g_bt + o1) = make_float2(b2v, b3v);
        }
    __syncthreads();                       // at/bt globally visible to CTA

    // chunk aggregates from L2: fwd (tid<128) || bwd (tid 128..255)
    if (tid < 128) {
        int h = tid;
        const float* pat = g_at + (size_t)n0 * H + h;
        const float* pbt = g_bt + (size_t)n0 * H + h;
        float A = 1.f, hf = 0.f;
        for (int t0 = 0; t0 < CL; t0 += 8) {
            float av[8], bv[8];
#pragma unroll
            for (int j = 0; j < 8; ++j) {
                av[j] = pat[(size_t)(t0 + j) * H];
                bv[j] = pbt[(size_t)(t0 + j) * H];
            }
#pragma unroll
            for (int j = 0; j < 8; ++j) { A *= av[j]; hf = fmaf(av[j], hf, bv[j]); }
        }
        int o = blockIdx.x * H + h;
        g_A[o] = A; g_Bf[o] = hf;
    } else if (tid < 256) {
        int h = tid - 128;
        const float* pat = g_at + (size_t)n0 * H + h;
        const float* pbt = g_bt + (size_t)n0 * H + h;
        float hb = 0.f;
        for (int t0 = CL - 8; t0 >= 0; t0 -= 8) {
            float av[8], bv[8];
#pragma unroll
            for (int j = 0; j < 8; ++j) {
                av[j] = pat[(size_t)(t0 + 7 - j) * H];
                bv[j] = pbt[(size_t)(t0 + 7 - j) * H];
            }
#pragma unroll
            for (int j = 0; j < 8; ++j) hb = fmaf(av[j], hb, bv[j]);
        }
        g_Bb[blockIdx.x * H + h] = hb;
    }
}

// ---------------- K5: per-CTA carry + scans + x1 = x + g1*([hf|hb]@Wout + b) ----------------
__global__ __launch_bounds__(512) void k_rout(const float* __restrict__ x,
                                              const float* __restrict__ bout) {
    extern __shared__ char sm[];
    float* sBias = (float*)(sm + OFF_BIAS);
    float* sC = (float*)(sm + OFF_A);      // bt -> hf -> bt -> hb
    int tid = threadIdx.x, wid = tid >> 5, lane = tid & 31;
    int wm = wid & 3, wn = wid >> 2, tr = lane >> 2, tc = lane & 3;
    int n0 = blockIdx.x * 128;
    int b = n0 >> 13;
    int bc = blockIdx.x;
    int bchunk = bc & (NCH - 1);
    int cbase = bc - bchunk;

    float cf = 0.f, cb = 0.f;
    if (tid < 128) {
        sBias[tid] = bout[tid];
        int h = tid;
        for (int i0 = 0; i0 < bchunk; i0 += 8) {
            float a[8], bf[8];
#pragma unroll
            for (int j = 0; j < 8; ++j) {
                int i = i0 + j;
                bool v = i < bchunk;
                int idx = (cbase + (v ? i : 0)) * H + h;
                a[j]  = v ? g_A[idx]  : 1.f;
                bf[j] = v ? g_Bf[idx] : 0.f;
            }
#pragma unroll
            for (int j = 0; j < 8; ++j) cf = fmaf(a[j], cf, bf[j]);
        }
    } else if (tid < 256) {
        int h = tid - 128;
        for (int i0 = NCH - 1; i0 > bchunk; i0 -= 8) {
            float a[8], bb_[8];
#pragma unroll
            for (int j = 0; j < 8; ++j) {
                int i = i0 - j;
                bool v = i > bchunk;
                int idx = (cbase + (v ? i : 0)) * H + h;
                a[j]   = v ? g_A[idx]  : 1.f;
                bb_[j] = v ? g_Bb[idx] : 0.f;
            }
#pragma unroll
            for (int j = 0; j < 8; ++j) cb = fmaf(a[j], cb, bb_[j]);
        }
    } else {
        // stage bt into sC
        int t = tid - 256;
        const float* gb = g_bt + (size_t)n0 * H;
#pragma unroll
        for (int it = 0; it < 16; ++it) {
            int idx = t + it * 256;
            int row = idx >> 5, j4 = (idx & 31) << 2;
            *(float4*)(sC + row * STRIDE + j4) = *(const float4*)(gb + (size_t)row * 128 + j4);
        }
    }
    // share cb with the bwd scan below (done by tid<128) via shuffle-free smem slot
    if (tid >= 128 && tid < 256) sBias[384 + (tid - 128)] = cb;
    __syncthreads();

    // forward scan in-place on sC -> tf32 hf
    if (tid < 128) {
        int h = tid;
        const float* ap = g_at + (size_t)n0 * H + h;
        float hf = cf;
        for (int t0 = 0; t0 < CL; t0 += 8) {
            float av[8];
#pragma unroll
            for (int j = 0; j < 8; ++j) av[j] = ap[(size_t)(t0 + j) * H];
#pragma unroll
            for (int j = 0; j < 8; ++j) {
                int t = t0 + j;
                hf = fmaf(av[j], hf, sC[t * STRIDE + h]);
                sC[t * STRIDE + h] = to_tf32(hf);
            }
        }
    }
    __syncthreads();

    float acc[2][4][4];
    ZACC(acc);
    wgemm_g(sC, g_WT[3], acc, wm, wn, lane);   // hf @ Wout_lo
    __syncthreads();

    // reload bt (all 512 threads)
    {
        const float* gb = g_bt + (size_t)n0 * H;
#pragma unroll
        for (int it = 0; it < 8; ++it) {
            int idx = tid + it * 512;
            int row = idx >> 5, j4 = (idx & 31) << 2;
            *(float4*)(sC + row * STRIDE + j4) = *(const float4*)(gb + (size_t)row * 128 + j4);
        }
    }
    __syncthreads();

    // backward scan in-place on sC -> tf32 hb
    if (tid < 128) {
        int h = tid;
        const float* ap = g_at + (size_t)n0 * H + h;
        float hb = sBias[384 + h];
        for (int t0 = CL - 8; t0 >= 0; t0 -= 8) {
            float av[8];
#pragma unroll
            for (int j = 0; j < 8; ++j) av[j] = ap[(size_t)(t0 + 7 - j) * H];
#pragma unroll
            for (int j = 0; j < 8; ++j) {
                int t = t0 + 7 - j;
                hb = fmaf(av[j], hb, sC[t * STRIDE + h]);
                sC[t * STRIDE + h] = to_tf32(hb);
            }
        }
    }
    __syncthreads();
    wgemm_g(sC, g_WT[4], acc, wm, wn, lane);   // hb @ Wout_hi

    float g1 = g_scal[b][2];
#pragma unroll
    for (int mt = 0; mt < 2; ++mt)
#pragma unroll
        for (int nt = 0; nt < 4; ++nt) {
            int r = wm * 32 + mt * 16 + tr, c = wn * 32 + nt * 8 + tc * 2;
            size_t o0 = (size_t)(n0 + r) * D + c, o1 = (size_t)(n0 + r + 8) * D + c;
            float2 x0 = *(const float2*)(x + o0);
            float2 x1v = *(const float2*)(x + o1);
            float2 w0, w1;
            w0.x = fmaf(g1, acc[mt][nt][0] + sBias[c],     x0.x);
            w0.y = fmaf(g1, acc[mt][nt][1] + sBias[c + 1], x0.y);
            w1.x = fmaf(g1, acc[mt][nt][2] + sBias[c],     x1v.x);
            w1.y = fmaf(g1, acc[mt][nt][3] + sBias[c + 1], x1v.y);
            *(float2*)(g_x1 + o0) = w0;
            *(float2*)(g_x1 + o1) = w1;
        }
}

// ---------------- K6: out = x1 + g2*(gelu(ln(x1)@W1+b1)@W2+b2) ----------------
__global__ __launch_bounds__(512) void k_mlp(float* __restrict__ out,
                                             const float* __restrict__ b1m,
                                             const float* __restrict__ b2m) {
    extern __shared__ char sm[];
    float* sBias = (float*)(sm + OFF_BIAS);
    float* sA = (float*)(sm + OFF_A);
    float* sC = (float*)(sm + OFF_C);
    int tid = threadIdx.x, wid = tid >> 5, lane = tid & 31;
    int wm = wid & 3, wn = wid >> 2, tr = lane >> 2, tc = lane & 3;
    int n0 = blockIdx.x * 128;
    int b = n0 >> 13;
    if (tid < 128) {
#pragma unroll
        for (int q = 0; q < 4; ++q) sBias[q * 128 + tid] = b1m[q * 128 + tid];
        sBias[512 + tid] = b2m[tid];
    }
    float s2p = 1.f + g_scal[b][3], b2s = g_scal[b][4], g2 = g_scal[b][5];

#pragma unroll
    for (int it = 0; it < 8; ++it) {
        int row = wid * 8 + it;
        const float* xp = g_x1 + (size_t)(n0 + row) * D;
        float v0 = xp[lane], v1 = xp[lane + 32], v2 = xp[lane + 64], v3 = xp[lane + 96];
        float m = warp_sum(v0 + v1 + v2 + v3) * (1.f / 128.f);
        float d0 = v0 - m, d1 = v1 - m, d2 = v2 - m, d3 = v3 - m;
        float rs = rsqrtf(warp_sum(d0*d0 + d1*d1 + d2*d2 + d3*d3) * (1.f / 128.f) + 1e-6f);
        float* ap = sA + row * STRIDE;
        ap[lane]      = to_tf32(fmaf(s2p, d0 * rs, b2s));
        ap[lane + 32] = to_tf32(fmaf(s2p, d1 * rs, b2s));
        ap[lane + 64] = to_tf32(fmaf(s2p, d2 * rs, b2s));
        ap[lane + 96] = to_tf32(fmaf(s2p, d3 * rs, b2s));
    }
    __syncthreads();

    float macc[2][4][4];
    ZACC(macc);
    for (int cc = 0; cc < 4; ++cc) {
        float tacc[2][4][4];
        ZACC(tacc);
        wgemm_g(sA, g_WT[5 + cc], tacc, wm, wn, lane);
        __syncthreads();                    // prev W2 gemm done reading sC
#pragma unroll
        for (int mt = 0; mt < 2; ++mt)
#pragma unroll
            for (int nt = 0; nt < 4; ++nt) {
                int r = wm * 32 + mt * 16 + tr, c = wn * 32 + nt * 8 + tc * 2;
                sC[r * STRIDE + c]           = to_tf32(geluf_(tacc[mt][nt][0] + sBias[cc * 128 + c]));
                sC[r * STRIDE + c + 1]       = to_tf32(geluf_(tacc[mt][nt][1] + sBias[cc * 128 + c + 1]));
                sC[(r + 8) * STRIDE + c]     = to_tf32(geluf_(tacc[mt][nt][2] + sBias[cc * 128 + c]));
                sC[(r + 8) * STRIDE + c + 1] = to_tf32(geluf_(tacc[mt][nt][3] + sBias[cc * 128 + c + 1]));
            }
        __syncthreads();
        wgemm_g(sC, g_WT[9 + cc], macc, wm, wn, lane);
    }

#pragma unroll
    for (int mt = 0; mt < 2; ++mt)
#pragma unroll
        for (int nt = 0; nt < 4; ++nt) {
            int r = wm * 32 + mt * 16 + tr, c = wn * 32 + nt * 8 + tc * 2;
            size_t o0 = (size_t)(n0 + r) * D + c, o1 = (size_t)(n0 + r + 8) * D + c;
            float2 x0 = *(const float2*)(g_x1 + o0);
            float2 x1v = *(const float2*)(g_x1 + o1);
            float2 w0, w1;
            w0.x = fmaf(g2, macc[mt][nt][0] + sBias[512 + c],     x0.x);
            w0.y = fmaf(g2, macc[mt][nt][1] + sBias[512 + c + 1], x0.y);
            w1.x = fmaf(g2, macc[mt][nt][2] + sBias[512 + c],     x1v.x);
            w1.y = fmaf(g2, macc[mt][nt][3] + sBias[512 + c + 1], x1v.y);
            *(float2*)(out + o0) = w0;
            *(float2*)(out + o1) = w1;
        }
}

// ---------------- launch ----------------
extern "C" void kernel_launch(void* const* d_in, const int* in_sizes, int n_in,
                              void* d_out, int out_size) {
    const float* x        = (const float*)d_in[0];
    const float* c        = (const float*)d_in[1];
    const float* cln1_sw  = (const float*)d_in[2];
    const float* cln1_sb  = (const float*)d_in[3];
    const float* cln1_bw  = (const float*)d_in[4];
    const float* cln1_bb  = (const float*)d_in[5];
    const float* gate1_w  = (const float*)d_in[6];
    const float* gate1_b  = (const float*)d_in[7];
    const float* rnn_in_w = (const float*)d_in[8];
    const float* rnn_in_b = (const float*)d_in[9];
    const float* pos_emb  = (const float*)d_in[10];
    const float* rnn_wi   = (const float*)d_in[11];
    const float* rnn_bi   = (const float*)d_in[12];
    const float* rnn_wr   = (const float*)d_in[13];
    const float* rnn_br   = (const float*)d_in[14];
    const float* rnn_a    = (const float*)d_in[15];
    const float* rnn_out_w= (const float*)d_in[16];
    const float* rnn_out_b= (const float*)d_in[17];
    const float* cln2_sw  = (const float*)d_in[18];
    const float* cln2_sb  = (const float*)d_in[19];
    const float* cln2_bw  = (const float*)d_in[20];
    const float* cln2_bb  = (const float*)d_in[21];
    const float* gate2_w  = (const float*)d_in[22];
    const float* gate2_b  = (const float*)d_in[23];
    const float* mlp_w1   = (const float*)d_in[24];
    const float* mlp_b1   = (const float*)d_in[25];
    const float* mlp_w2   = (const float*)d_in[26];
    const float* mlp_b2   = (const float*)d_in[27];
    float* out = (float*)d_out;

    cudaFuncSetAttribute(k_front, cudaFuncAttributeMaxDynamicSharedMemorySize, SMEM_FR);
    cudaFuncSetAttribute(k_rout,  cudaFuncAttributeMaxDynamicSharedMemorySize, SMEM_FR);
    cudaFuncSetAttribute(k_mlp,   cudaFuncAttributeMaxDynamicSharedMemorySize, SMEM_MLP);

    k_scal<<<1, 256>>>(c, cln1_sw, cln1_sb, cln1_bw, cln1_bb, gate1_w, gate1_b,
                       cln2_sw, cln2_sb, cln2_bw, cln2_bb, gate2_w, gate2_b, rnn_a);
    k_prep<<<52, 256>>>(rnn_in_w, rnn_wi, rnn_wr, rnn_out_w, mlp_w1, mlp_w2);
    k_front<<<NTOK / 128, 512, SMEM_FR>>>(x, pos_emb, rnn_in_b, rnn_bi, rnn_br);
    k_rout<<<NTOK / 128, 512, SMEM_FR>>>(x, rnn_out_b);
    k_mlp<<<NTOK / 128, 512, SMEM_MLP>>>(out, mlp_b1, mlp_b2);
}

// round 16
// speedup vs baseline: 1.0455x; 1.0455x over previous
#include <cuda_runtime.h>
#include <math.h>
#include <stdint.h>

#define BS   8
#define LSEQ 8192
#define D    128
#define H    128
#define NTOK (BS * LSEQ)
#define CL   128
#define NCH  (LSEQ / CL)   // 64

#define STRIDE    136                       // floats per smem tile row (8-float pad)
#define TILE_B    (128 * STRIDE * 4)        // 69632 bytes
#define OFF_BIAS  0
#define OFF_A     4096
#define OFF_B     (OFF_A + TILE_B)
#define OFF_C     (OFF_B + TILE_B)
#define SMEM_SZ   (OFF_C + TILE_B)          // 212992

// ---------------- device scratch ----------------
__device__ __align__(16) float g_scal[BS][6];
__device__ __align__(16) float g_loga[H];          // log2(a)
__device__ __align__(16) float g_WT[13][16384];    // col-permuted transposed tf32 weights
__device__ __align__(16) float g_at[(size_t)NTOK * H];
__device__ __align__(16) float g_bt[(size_t)NTOK * H];
__device__ __align__(16) float g_x1[(size_t)NTOK * D];
__device__ __align__(16) float g_A [BS * NCH * H];
__device__ __align__(16) float g_Bf[BS * NCH * H];
__device__ __align__(16) float g_Bb[BS * NCH * H];

// ---------------- helpers ----------------
// column-pair permutation: logical k -> physical col; puts (k, k+4) adjacent
__device__ __forceinline__ int cperm(int k) {
    return (k & ~7) | (((k & 3) << 1) | ((k >> 2) & 1));
}
__device__ __forceinline__ float to_tf32(float x) {
    uint32_t u;
    asm("cvt.rna.tf32.f32 %0, %1;" : "=r"(u) : "f"(x));
    return __uint_as_float(u);
}
__device__ __forceinline__ float fast_ex2(float x) { float y; asm("ex2.approx.f32 %0, %1;" : "=f"(y) : "f"(x)); return y; }
__device__ __forceinline__ float fast_rcp(float x) { float y; asm("rcp.approx.f32 %0, %1;" : "=f"(y) : "f"(x)); return y; }
__device__ __forceinline__ float sigf(float v) { return fast_rcp(1.f + fast_ex2(-1.4426950408889634f * v)); }
__device__ __forceinline__ float tanh_(float x) { return 1.f - 2.f * fast_rcp(1.f + fast_ex2(2.8853900817779268f * x)); }
__device__ __forceinline__ float geluf_(float v) {
    float v3 = v * v * v;
    return 0.5f * v * (1.f + tanh_(0.7978845608028654f * (v + 0.044715f * v3)));
}
__device__ __forceinline__ float warp_sum(float v) {
    v += __shfl_xor_sync(0xffffffffu, v, 16);
    v += __shfl_xor_sync(0xffffffffu, v, 8);
    v += __shfl_xor_sync(0xffffffffu, v, 4);
    v += __shfl_xor_sync(0xffffffffu, v, 2);
    v += __shfl_xor_sync(0xffffffffu, v, 1);
    return v;
}

#define MMA168(c, a, b0, b1)                                                        \
    asm volatile("mma.sync.aligned.m16n8k8.row.col.f32.tf32.tf32.f32 "              \
                 "{%0,%1,%2,%3}, {%4,%5,%6,%7}, {%8,%9}, {%0,%1,%2,%3};"            \
                 : "+f"((c)[0]), "+f"((c)[1]), "+f"((c)[2]), "+f"((c)[3])           \
                 : "r"((a)[0]), "r"((a)[1]), "r"((a)[2]), "r"((a)[3]),              \
                   "r"(b0), "r"(b1))

#define ZACC(a) do {                                                                \
    _Pragma("unroll") for (int _m = 0; _m < 2; ++_m)                                \
    _Pragma("unroll") for (int _n = 0; _n < 4; ++_n)                                \
    _Pragma("unroll") for (int _q = 0; _q < 4; ++_q) (a)[_m][_n][_q] = 0.f;         \
} while (0)

// warp GEMM on col-permuted tiles: 32x32 patch, fragment pairs via lds.64
__device__ __forceinline__ void wgemm(const float* __restrict__ sA,
                                      const float* __restrict__ sB,
                                      float (&acc)[2][4][4],
                                      int wm, int wn, int tr, int tc) {
#pragma unroll 4
    for (int ks = 0; ks < 16; ++ks) {
        int k0 = ks * 8;
        uint32_t a[2][4];
#pragma unroll
        for (int mt = 0; mt < 2; ++mt) {
            const float* ap = sA + (wm * 32 + mt * 16 + tr) * STRIDE + k0 + tc * 2;
            float2 a0 = *(const float2*)ap;                      // logical (tc, tc+4)
            float2 a1 = *(const float2*)(ap + 8 * STRIDE);
            a[mt][0] = __float_as_uint(a0.x);
            a[mt][1] = __float_as_uint(a1.x);
            a[mt][2] = __float_as_uint(a0.y);
            a[mt][3] = __float_as_uint(a1.y);
        }
#pragma unroll
        for (int nt = 0; nt < 4; ++nt) {
            float2 bv = *(const float2*)(sB + (wn * 32 + nt * 8 + tr) * STRIDE + k0 + tc * 2);
            uint32_t b0 = __float_as_uint(bv.x), b1 = __float_as_uint(bv.y);
#pragma unroll
            for (int mt = 0; mt < 2; ++mt) MMA168(acc[mt][nt], a[mt], b0, b1);
        }
    }
}

// copy a prepared (already permuted) 128x128 tf32 tile into smem with STRIDE rows
__device__ __forceinline__ void cp_tileT(float* dst, const float* __restrict__ src, int tid) {
#pragma unroll
    for (int it = 0; it < 8; ++it) {
        int idx = tid + it * 512;              // float4 index
        int row = idx >> 5, j = idx & 31;
        *(float4*)(dst + row * STRIDE + j * 4) = ((const float4*)src)[idx];
    }
}
// stage a 128x128 fp32 row-major global tile into permuted smem (scalar stores)
__device__ __forceinline__ void stage_perm(float* dst, const float* __restrict__ g, int t, int nthr) {
    for (int idx = t; idx < 4096; idx += nthr) {
        int row = idx >> 5, j4 = (idx & 31) << 2;
        float4 v = *(const float4*)(g + (size_t)row * 128 + j4);
        int pb = (j4 & ~7) + ((j4 >> 2) & 1);          // perm base for j4..j4+3 (stride 2)
        float* d = dst + row * STRIDE + pb;
        d[0] = v.x; d[2] = v.y; d[4] = v.z; d[6] = v.w;
    }
}

// ---------------- K0: conditioning scalars + log2(a) ----------------
__global__ void k_scal(const float* __restrict__ c,
                       const float* sw1, const float* sb1, const float* bw1, const float* bb1,
                       const float* gw1, const float* gb1, const float* sw2, const float* sb2,
                       const float* bw2, const float* bb2, const float* gw2, const float* gb2,
                       const float* __restrict__ a) {
    int tid = threadIdx.x;
    if (tid < 48) {
        const float* ws[6] = {sw1, bw1, gw1, sw2, bw2, gw2};
        const float* bs[6] = {sb1, bb1, gb1, sb2, bb2, gb2};
        int b = tid / 6, j = tid % 6;
        float s = bs[j][0];
        const float* cp = c + b * 128;
        for (int k = 0; k < 128; ++k) s = fmaf(cp[k], ws[j][k], s);
        g_scal[b][j] = s;
    }
    int i = tid - 64;
    if (i >= 0 && i < H) g_loga[i] = log2f(a[i]);
}

// ---------------- K-prep: transposed + column-permuted tf32 weight tiles ----------------
// 0=Win 1=Wi 2=Wr 3=Wout(k<128) 4=Wout(k>=128) 5..8=W1 chunks 9..12=W2 chunks
__global__ void k_prep(const float* __restrict__ Win, const float* __restrict__ Wi,
                       const float* __restrict__ Wr, const float* __restrict__ Wout,
                       const float* __restrict__ W1, const float* __restrict__ W2) {
    int t = blockIdx.x >> 2, quarter = blockIdx.x & 3, tid = threadIdx.x;
    for (int i = quarter * 16; i < quarter * 16 + 16; ++i) {
        int e = i * 256 + tid;
        int n = e >> 7, k = e & 127;
        float v;
        if (t == 0)      v = Win[k * 128 + n];
        else if (t == 1) v = Wi[k * 128 + n];
        else if (t == 2) v = Wr[k * 128 + n];
        else if (t == 3) v = Wout[k * 128 + n];
        else if (t == 4) v = Wout[(128 + k) * 128 + n];
        else if (t < 9)  v = W1[k * 512 + (t - 5) * 128 + n];
        else             v = W2[((t - 9) * 128 + k) * 128 + n];
        g_WT[t][n * 128 + cperm(k)] = to_tf32(v);
    }
}

// ---------------- K1: x -> (at, bt) + chunk scan aggregates ----------------
__global__ __launch_bounds__(512, 1) void k_front(
    const float* __restrict__ x, const float* __restrict__ pos,
    const float* __restrict__ inb, const float* __restrict__ bi,
    const float* __restrict__ br) {
    extern __shared__ char sm[];
    float* sBias = (float*)(sm + OFF_BIAS);
    float* sA = (float*)(sm + OFF_A);
    float* sB = (float*)(sm + OFF_B);
    float* sC = (float*)(sm + OFF_C);
    int tid = threadIdx.x, wid = tid >> 5, lane = tid & 31;
    int wm = wid & 3, wn = wid >> 2, tr = lane >> 2, tc = lane & 3;
    int n0 = blockIdx.x * 128;
    int b = n0 >> 13, l0 = n0 & (LSEQ - 1);
    int cl = cperm(lane);
    if (tid < 128) {
        sBias[tid] = inb[tid]; sBias[128 + tid] = bi[tid];
        sBias[256 + tid] = br[tid]; sBias[384 + tid] = g_loga[tid];
    }
    float s1p = 1.f + g_scal[b][0], b1s = g_scal[b][1];

    // conditioned double-LN -> permuted tf32 A tile
#pragma unroll
    for (int it = 0; it < 8; ++it) {
        int row = wid * 8 + it;
        const float* xp = x + (size_t)(n0 + row) * D;
        float v0 = xp[lane], v1 = xp[lane + 32], v2 = xp[lane + 64], v3 = xp[lane + 96];
        float m = warp_sum(v0 + v1 + v2 + v3) * (1.f / 128.f);
        float d0 = v0 - m, d1 = v1 - m, d2 = v2 - m, d3 = v3 - m;
        float rs = rsqrtf(warp_sum(d0*d0 + d1*d1 + d2*d2 + d3*d3) * (1.f / 128.f) + 1e-6f);
        float h0 = fmaf(s1p, d0 * rs, b1s), h1 = fmaf(s1p, d1 * rs, b1s);
        float h2 = fmaf(s1p, d2 * rs, b1s), h3 = fmaf(s1p, d3 * rs, b1s);
        float m2 = warp_sum(h0 + h1 + h2 + h3) * (1.f / 128.f);
        float e0 = h0 - m2, e1 = h1 - m2, e2 = h2 - m2, e3 = h3 - m2;
        float rs2 = rsqrtf(warp_sum(e0*e0 + e1*e1 + e2*e2 + e3*e3) * (1.f / 128.f) + 1e-6f);
        float* ap = sA + row * STRIDE;
        ap[cl]      = to_tf32(e0 * rs2);
        ap[cl + 32] = to_tf32(e1 * rs2);
        ap[cl + 64] = to_tf32(e2 * rs2);
        ap[cl + 96] = to_tf32(e3 * rs2);
    }
    cp_tileT(sB, g_WT[0], tid);            // Win
    cp_tileT(sC, g_WT[1], tid);            // Wi (hoisted)
    __syncthreads();

    float uacc[2][4][4];
    ZACC(uacc);
    wgemm(sA, sB, uacc, wm, wn, tr, tc);
    __syncthreads();                       // all warps done reading sA / sB

    // u = gemm + bias + pos -> tf32 back into sA (permuted); Wr -> sB concurrently
#pragma unroll
    for (int mt = 0; mt < 2; ++mt)
#pragma unroll
        for (int nt = 0; nt < 4; ++nt) {
            int r = wm * 32 + mt * 16 + tr, c = wn * 32 + nt * 8 + tc * 2;
            int p0 = cperm(c), p1 = cperm(c + 1);
            float2 pp0 = *(const float2*)(pos + (size_t)(l0 + r) * H + c);
            float2 pp1 = *(const float2*)(pos + (size_t)(l0 + r + 8) * H + c);
            sA[r * STRIDE + p0]       = to_tf32(uacc[mt][nt][0] + sBias[c]     + pp0.x);
            sA[r * STRIDE + p1]       = to_tf32(uacc[mt][nt][1] + sBias[c + 1] + pp0.y);
            sA[(r + 8) * STRIDE + p0] = to_tf32(uacc[mt][nt][2] + sBias[c]     + pp1.x);
            sA[(r + 8) * STRIDE + p1] = to_tf32(uacc[mt][nt][3] + sBias[c + 1] + pp1.y);
        }
    cp_tileT(sB, g_WT[2], tid);            // Wr
    __syncthreads();

    float gacc[2][4][4];
    ZACC(gacc);
    wgemm(sA, sC, gacc, wm, wn, tr, tc);   // input gate (Wi)
#pragma unroll
    for (int mt = 0; mt < 2; ++mt)
#pragma unroll
        for (int nt = 0; nt < 4; ++nt) {
            int c = wn * 32 + nt * 8 + tc * 2;
            gacc[mt][nt][0] = sigf(gacc[mt][nt][0] + sBias[128 + c]);
            gacc[mt][nt][1] = sigf(gacc[mt][nt][1] + sBias[128 + c + 1]);
            gacc[mt][nt][2] = sigf(gacc[mt][nt][2] + sBias[128 + c]);
            gacc[mt][nt][3] = sigf(gacc[mt][nt][3] + sBias[128 + c + 1]);
        }
    float racc[2][4][4];
    ZACC(racc);
    wgemm(sA, sB, racc, wm, wn, tr, tc);   // recurrence gate (Wr)
    __syncthreads();                       // sB/sC free for at/bt staging

#pragma unroll
    for (int mt = 0; mt < 2; ++mt)
#pragma unroll
        for (int nt = 0; nt < 4; ++nt) {
            int r = wm * 32 + mt * 16 + tr, c = wn * 32 + nt * 8 + tc * 2;
            int p0 = cperm(c), p1 = cperm(c + 1);
            float u00 = sA[r * STRIDE + p0],       u01 = sA[r * STRIDE + p1];
            float u10 = sA[(r + 8) * STRIDE + p0], u11 = sA[(r + 8) * STRIDE + p1];
            float la0 = sBias[384 + c], la1 = sBias[384 + c + 1];
            float gr0 = sigf(racc[mt][nt][0] + sBias[256 + c]);
            float gr1 = sigf(racc[mt][nt][1] + sBias[256 + c + 1]);
            float gr2 = sigf(racc[mt][nt][2] + sBias[256 + c]);
            float gr3 = sigf(racc[mt][nt][3] + sBias[256 + c + 1]);
            float a0 = fast_ex2(8.f * gr0 * la0);
            float a1 = fast_ex2(8.f * gr1 * la1);
            float a2 = fast_ex2(8.f * gr2 * la0);
            float a3 = fast_ex2(8.f * gr3 * la1);
            float b0v = sqrtf(fmaxf(0.f, 1.f - a0 * a0)) * gacc[mt][nt][0] * u00;
            float b1v = sqrtf(fmaxf(0.f, 1.f - a1 * a1)) * gacc[mt][nt][1] * u01;
            float b2v = sqrtf(fmaxf(0.f, 1.f - a2 * a2)) * gacc[mt][nt][2] * u10;
            float b3v = sqrtf(fmaxf(0.f, 1.f - a3 * a3)) * gacc[mt][nt][3] * u11;
            size_t o0 = (size_t)(n0 + r) * H + c, o1 = (size_t)(n0 + r + 8) * H + c;
            *(float2*)(g_at + o0) = make_float2(a0, a1);
            *(float2*)(g_at + o1) = make_float2(a2, a3);
            *(float2*)(g_bt + o0) = make_float2(b0v, b1v);
            *(float2*)(g_bt + o1) = make_float2(b2v, b3v);
            // stage (permuted) into smem for the chunk-local scan
            sB[r * STRIDE + p0] = a0;  sB[r * STRIDE + p1] = a1;
            sB[(r + 8) * STRIDE + p0] = a2;  sB[(r + 8) * STRIDE + p1] = a3;
            sC[r * STRIDE + p0] = b0v; sC[r * STRIDE + p1] = b1v;
            sC[(r + 8) * STRIDE + p0] = b2v; sC[(r + 8) * STRIDE + p1] = b3v;
        }
    __syncthreads();

    // chunk aggregates: fwd (tid<128) || bwd (tid 128..255); col h -> cperm(h)
    if (tid < 128) {
        int h = tid, ph = cperm(tid);
        float A = 1.f, hf = 0.f;
#pragma unroll 4
        for (int t = 0; t < CL; ++t) {
            float a = sB[t * STRIDE + ph], bv = sC[t * STRIDE + ph];
            A *= a;
            hf = fmaf(a, hf, bv);
        }
        int o = blockIdx.x * H + h;
        g_A[o] = A; g_Bf[o] = hf;
    } else if (tid < 256) {
        int h = tid - 128, ph = cperm(h);
        float hb = 0.f;
#pragma unroll 4
        for (int t = CL - 1; t >= 0; --t)
            hb = fmaf(sB[t * STRIDE + ph], hb, sC[t * STRIDE + ph]);
        g_Bb[blockIdx.x * H + h] = hb;
    }
}

// ---------------- K5: per-CTA carry + scans + x1 = x + g1*([hf|hb]@Wout + b) ----------------
__global__ __launch_bounds__(512, 1) void k_rout(const float* __restrict__ x,
                                                 const float* __restrict__ bout) {
    extern __shared__ char sm[];
    float* sBias = (float*)(sm + OFF_BIAS);
    float* sA = (float*)(sm + OFF_A);      // weights
    float* sC = (float*)(sm + OFF_C);      // bt -> hf -> bt -> hb (permuted)
    int tid = threadIdx.x, wid = tid >> 5, lane = tid & 31;
    int wm = wid & 3, wn = wid >> 2, tr = lane >> 2, tc = lane & 3;
    int n0 = blockIdx.x * 128;
    int b = n0 >> 13;
    int bc = blockIdx.x;
    int bchunk = bc & (NCH - 1);
    int cbase = bc - bchunk;

    float cf = 0.f, cb = 0.f;
    if (tid < 128) {
        sBias[tid] = bout[tid];
        int h = tid;
        for (int i0 = 0; i0 < bchunk; i0 += 8) {
            float a[8], bf[8];
#pragma unroll
            for (int j = 0; j < 8; ++j) {
                int i = i0 + j;
                bool v = i < bchunk;
                int idx = (cbase + (v ? i : 0)) * H + h;
                a[j]  = v ? g_A[idx]  : 1.f;
                bf[j] = v ? g_Bf[idx] : 0.f;
            }
#pragma unroll
            for (int j = 0; j < 8; ++j) cf = fmaf(a[j], cf, bf[j]);
        }
    } else if (tid < 256) {
        int h = tid - 128;
        for (int i0 = NCH - 1; i0 > bchunk; i0 -= 8) {
            float a[8], bb_[8];
#pragma unroll
            for (int j = 0; j < 8; ++j) {
                int i = i0 - j;
                bool v = i > bchunk;
                int idx = (cbase + (v ? i : 0)) * H + h;
                a[j]   = v ? g_A[idx]  : 1.f;
                bb_[j] = v ? g_Bb[idx] : 0.f;
            }
#pragma unroll
            for (int j = 0; j < 8; ++j) cb = fmaf(a[j], cb, bb_[j]);
        }
        sBias[384 + (tid - 128)] = cb;
    } else {
        // stage bt (permuted) into sC; stage W3 into sA
        stage_perm(sC, g_bt + (size_t)n0 * H, tid - 256, 256);
        for (int idx = tid - 256; idx < 4096; idx += 256) {
            int row = idx >> 5, j = idx & 31;
            *(float4*)(sA + row * STRIDE + j * 4) = ((const float4*)g_WT[3])[idx];
        }
    }
    __syncthreads();

    // forward scan in-place on sC -> tf32 hf
    if (tid < 128) {
        int h = tid, ph = cperm(tid);
        const float* ap = g_at + (size_t)n0 * H + h;
        float hf = cf;
        for (int t0 = 0; t0 < CL; t0 += 8) {
            float av[8];
#pragma unroll
            for (int j = 0; j < 8; ++j) av[j] = ap[(size_t)(t0 + j) * H];
#pragma unroll
            for (int j = 0; j < 8; ++j) {
                int t = t0 + j;
                hf = fmaf(av[j], hf, sC[t * STRIDE + ph]);
                sC[t * STRIDE + ph] = to_tf32(hf);
            }
        }
    }
    __syncthreads();

    float acc[2][4][4];
    ZACC(acc);
    wgemm(sC, sA, acc, wm, wn, tr, tc);    // hf @ Wout_lo
    __syncthreads();

    // reload bt (permuted, all 512) + W4 -> sA
    stage_perm(sC, g_bt + (size_t)n0 * H, tid, 512);
    cp_tileT(sA, g_WT[4], tid);
    __syncthreads();

    // backward scan in-place on sC -> tf32 hb
    if (tid < 128) {
        int h = tid, ph = cperm(tid);
        const float* ap = g_at + (size_t)n0 * H + h;
        float hb = sBias[384 + h];
        for (int t0 = CL - 8; t0 >= 0; t0 -= 8) {
            float av[8];
#pragma unroll
            for (int j = 0; j < 8; ++j) av[j] = ap[(size_t)(t0 + 7 - j) * H];
#pragma unroll
            for (int j = 0; j < 8; ++j) {
                int t = t0 + 7 - j;
                hb = fmaf(av[j], hb, sC[t * STRIDE + ph]);
                sC[t * STRIDE + ph] = to_tf32(hb);
            }
        }
    }
    __syncthreads();
    wgemm(sC, sA, acc, wm, wn, tr, tc);    // hb @ Wout_hi

    float g1 = g_scal[b][2];
#pragma unroll
    for (int mt = 0; mt < 2; ++mt)
#pragma unroll
        for (int nt = 0; nt < 4; ++nt) {
            int r = wm * 32 + mt * 16 + tr, c = wn * 32 + nt * 8 + tc * 2;
            size_t o0 = (size_t)(n0 + r) * D + c, o1 = (size_t)(n0 + r + 8) * D + c;
            float2 x0 = *(const float2*)(x + o0);
            float2 x1v = *(const float2*)(x + o1);
            float2 w0, w1;
            w0.x = fmaf(g1, acc[mt][nt][0] + sBias[c],     x0.x);
            w0.y = fmaf(g1, acc[mt][nt][1] + sBias[c + 1], x0.y);
            w1.x = fmaf(g1, acc[mt][nt][2] + sBias[c],     x1v.x);
            w1.y = fmaf(g1, acc[mt][nt][3] + sBias[c + 1], x1v.y);
            *(float2*)(g_x1 + o0) = w0;
            *(float2*)(g_x1 + o1) = w1;
        }
}

// ---------------- K6: out = x1 + g2*(gelu(ln(x1)@W1+b1)@W2+b2) ----------------
__global__ __launch_bounds__(512, 1) void k_mlp(float* __restrict__ out,
                                                const float* __restrict__ b1m,
                                                const float* __restrict__ b2m) {
    extern __shared__ char sm[];
    float* sBias = (float*)(sm + OFF_BIAS);
    float* sA = (float*)(sm + OFF_A);
    float* sB = (float*)(sm + OFF_B);
    float* sC = (float*)(sm + OFF_C);
    int tid = threadIdx.x, wid = tid >> 5, lane = tid & 31;
    int wm = wid & 3, wn = wid >> 2, tr = lane >> 2, tc = lane & 3;
    int n0 = blockIdx.x * 128;
    int b = n0 >> 13;
    int cl = cperm(lane);
    if (tid < 128) {
#pragma unroll
        for (int q = 0; q < 4; ++q) sBias[q * 128 + tid] = b1m[q * 128 + tid];
        sBias[512 + tid] = b2m[tid];
    }
    float s2p = 1.f + g_scal[b][3], b2s = g_scal[b][4], g2 = g_scal[b][5];

#pragma unroll
    for (int it = 0; it < 8; ++it) {
        int row = wid * 8 + it;
        const float* xp = g_x1 + (size_t)(n0 + row) * D;
        float v0 = xp[lane], v1 = xp[lane + 32], v2 = xp[lane + 64], v3 = xp[lane + 96];
        float m = warp_sum(v0 + v1 + v2 + v3) * (1.f / 128.f);
        float d0 = v0 - m, d1 = v1 - m, d2 = v2 - m, d3 = v3 - m;
        float rs = rsqrtf(warp_sum(d0*d0 + d1*d1 + d2*d2 + d3*d3) * (1.f / 128.f) + 1e-6f);
        float* ap = sA + row * STRIDE;
        ap[cl]      = to_tf32(fmaf(s2p, d0 * rs, b2s));
        ap[cl + 32] = to_tf32(fmaf(s2p, d1 * rs, b2s));
        ap[cl + 64] = to_tf32(fmaf(s2p, d2 * rs, b2s));
        ap[cl + 96] = to_tf32(fmaf(s2p, d3 * rs, b2s));
    }

    float macc[2][4][4];
    ZACC(macc);
    for (int cc = 0; cc < 4; ++cc) {
        cp_tileT(sB, g_WT[5 + cc], tid);
        __syncthreads();
        float tacc[2][4][4];
        ZACC(tacc);
        wgemm(sA, sB, tacc, wm, wn, tr, tc);
        __syncthreads();                    // done with sB (and prev sC reads)
#pragma unroll
        for (int mt = 0; mt < 2; ++mt)
#pragma unroll
            for (int nt = 0; nt < 4; ++nt) {
                int r = wm * 32 + mt * 16 + tr, c = wn * 32 + nt * 8 + tc * 2;
                int p0 = cperm(c), p1 = cperm(c + 1);
                sC[r * STRIDE + p0]       = to_tf32(geluf_(tacc[mt][nt][0] + sBias[cc * 128 + c]));
                sC[r * STRIDE + p1]       = to_tf32(geluf_(tacc[mt][nt][1] + sBias[cc * 128 + c + 1]));
                sC[(r + 8) * STRIDE + p0] = to_tf32(geluf_(tacc[mt][nt][2] + sBias[cc * 128 + c]));
                sC[(r + 8) * STRIDE + p1] = to_tf32(geluf_(tacc[mt][nt][3] + sBias[cc * 128 + c + 1]));
            }
        cp_tileT(sB, g_WT[9 + cc], tid);
        __syncthreads();
        wgemm(sC, sB, macc, wm, wn, tr, tc);
        __syncthreads();                    // before next W1 overwrite of sB
    }

#pragma unroll
    for (int mt = 0; mt < 2; ++mt)
#pragma unroll
        for (int nt = 0; nt < 4; ++nt) {
            int r = wm * 32 + mt * 16 + tr, c = wn * 32 + nt * 8 + tc * 2;
            size_t o0 = (size_t)(n0 + r) * D + c, o1 = (size_t)(n0 + r + 8) * D + c;
            float2 x0 = *(const float2*)(g_x1 + o0);
            float2 x1v = *(const float2*)(g_x1 + o1);
            float2 w0, w1;
            w0.x = fmaf(g2, macc[mt][nt][0] + sBias[512 + c],     x0.x);
            w0.y = fmaf(g2, macc[mt][nt][1] + sBias[512 + c + 1], x0.y);
            w1.x = fmaf(g2, macc[mt][nt][2] + sBias[512 + c],     x1v.x);
            w1.y = fmaf(g2, macc[mt][nt][3] + sBias[512 + c + 1], x1v.y);
            *(float2*)(out + o0) = w0;
            *(float2*)(out + o1) = w1;
        }
}

// ---------------- launch ----------------
extern "C" void kernel_launch(void* const* d_in, const int* in_sizes, int n_in,
                              void* d_out, int out_size) {
    const float* x        = (const float*)d_in[0];
    const float* c        = (const float*)d_in[1];
    const float* cln1_sw  = (const float*)d_in[2];
    const float* cln1_sb  = (const float*)d_in[3];
    const float* cln1_bw  = (const float*)d_in[4];
    const float* cln1_bb  = (const float*)d_in[5];
    const float* gate1_w  = (const float*)d_in[6];
    const float* gate1_b  = (const float*)d_in[7];
    const float* rnn_in_w = (const float*)d_in[8];
    const float* rnn_in_b = (const float*)d_in[9];
    const float* pos_emb  = (const float*)d_in[10];
    const float* rnn_wi   = (const float*)d_in[11];
    const float* rnn_bi   = (const float*)d_in[12];
    const float* rnn_wr   = (const float*)d_in[13];
    const float* rnn_br   = (const float*)d_in[14];
    const float* rnn_a    = (const float*)d_in[15];
    const float* rnn_out_w= (const float*)d_in[16];
    const float* rnn_out_b= (const float*)d_in[17];
    const float* cln2_sw  = (const float*)d_in[18];
    const float* cln2_sb  = (const float*)d_in[19];
    const float* cln2_bw  = (const float*)d_in[20];
    const float* cln2_bb  = (const float*)d_in[21];
    const float* gate2_w  = (const float*)d_in[22];
    const float* gate2_b  = (const float*)d_in[23];
    const float* mlp_w1   = (const float*)d_in[24];
    const float* mlp_b1   = (const float*)d_in[25];
    const float* mlp_w2   = (const float*)d_in[26];
    const float* mlp_b2   = (const float*)d_in[27];
    float* out = (float*)d_out;

    cudaFuncSetAttribute(k_front, cudaFuncAttributeMaxDynamicSharedMemorySize, SMEM_SZ);
    cudaFuncSetAttribute(k_rout,  cudaFuncAttributeMaxDynamicSharedMemorySize, SMEM_SZ);
    cudaFuncSetAttribute(k_mlp,   cudaFuncAttributeMaxDynamicSharedMemorySize, SMEM_SZ);

    k_scal<<<1, 256>>>(c, cln1_sw, cln1_sb, cln1_bw, cln1_bb, gate1_w, gate1_b,
                       cln2_sw, cln2_sb, cln2_bw, cln2_bb, gate2_w, gate2_b, rnn_a);
    k_prep<<<52, 256>>>(rnn_in_w, rnn_wi, rnn_wr, rnn_out_w, mlp_w1, mlp_w2);
    k_front<<<NTOK / 128, 512, SMEM_SZ>>>(x, pos_emb, rnn_in_b, rnn_bi, rnn_br);
    k_rout<<<NTOK / 128, 512, SMEM_SZ>>>(x, rnn_out_b);
    k_mlp<<<NTOK / 128, 512, SMEM_SZ>>>(out, mlp_b1, mlp_b2);
}